// round 11
// baseline (speedup 1.0000x reference)
#include <cuda_runtime.h>
#include <math.h>
#include <float.h>

// Problem constants
#define NS 25      // support count (WAY*SHOT)
#define NQ 75      // query count (WAY*QUERY_SHOT)
#define DD 640     // feature dim
#define MM 25      // M (inner dim)

#define NPROD 250  // producer blocks: 25 s x 10 d-chunks of 64
#define NCONS 375  // consumer blocks: 75 q x 5 d-chunks of 128

// Scratch (device globals; flags return to 0 within each launch)
__device__ float g_P[NQ * NS * DD];    // P[q][s][d] = sum_m S[s,d,m]*W[s,q,m]
__device__ float g_part[NQ * NS * 8];  // per-(q,s): 5 chunk partials (pad 8)
__device__ int   g_prod[16];           // producer-done count per d-chunk64
__device__ int   g_cons[8];            // consumer-done count per d-chunk128

struct SmemProd {                      // 14.8 KB
    float W[MM][80];                   // [m][q], zero-padded to 80
    float S[MM][68];                   // [m][d64] (+pad)
};
struct SmemCons {                      // 16.8 KB
    float W[MM][36];                   // [m][s], zero-padded to 36
    float Q[MM][132];                  // [m][d128] (+pad)
};

// ---------------------------------------------------------------------------
// Fused kernel: 625 blocks x 256 threads, ALL co-resident (>=5 blocks/SM
// guaranteed by __launch_bounds__(256,5): threads 2048/256=8, smem 227/16.9,
// regs<=51 -> >=5). Producers and consumers overlap; consumers spin on
// per-chunk flags only after finishing their own independent r-GEMM.
// ---------------------------------------------------------------------------
__global__ __launch_bounds__(256, 5) void fused_pc(
        const float* __restrict__ fm, const float* __restrict__ w2) {
    __shared__ __align__(16) union { SmemProd p; SmemCons c; } sm;

    const int bid  = blockIdx.x;
    const int tid  = threadIdx.x;
    const int lane = tid & 31;
    const int warp = tid >> 5;   // 0..7

    if (bid < NPROD) {
        // ================= Producer: (s, d-chunk64) =========================
        const int s  = bid / 10;
        const int c  = bid - s * 10;
        const int d0 = c * 64;

        for (int idx = tid; idx < NQ * MM; idx += 256) {
            int q = idx / MM, m = idx - (idx / MM) * MM;
            sm.p.W[m][q] = w2[s * (NQ * MM) + idx];
        }
        for (int idx = tid; idx < 5 * MM; idx += 256) {   // zero-pad q=75..79
            int m = idx % MM, q = NQ + idx / MM;
            sm.p.W[m][q] = 0.0f;
        }
        for (int idx = tid; idx < 64 * MM; idx += 256) {
            int d = idx / MM, m = idx - (idx / MM) * MM;
            sm.p.S[m][d] = fm[s * (DD * MM) + d0 * MM + idx];
        }
        __syncthreads();

        const int qb = warp * 10;   // q base (0..70); warp 7 partly padded

        float acc[10][2];
#pragma unroll
        for (int j = 0; j < 10; j++) { acc[j][0] = 0.0f; acc[j][1] = 0.0f; }

#pragma unroll
        for (int m = 0; m < MM; m++) {
            float2 bv = *reinterpret_cast<const float2*>(&sm.p.S[m][lane * 2]);
#pragma unroll
            for (int jj = 0; jj < 5; jj++) {
                float2 av = *reinterpret_cast<const float2*>(
                    &sm.p.W[m][qb + 2 * jj]);               // LDS.64 broadcast
                acc[2*jj][0]   = fmaf(av.x, bv.x, acc[2*jj][0]);
                acc[2*jj][1]   = fmaf(av.x, bv.y, acc[2*jj][1]);
                acc[2*jj+1][0] = fmaf(av.y, bv.x, acc[2*jj+1][0]);
                acc[2*jj+1][1] = fmaf(av.y, bv.y, acc[2*jj+1][1]);
            }
        }

#pragma unroll
        for (int j = 0; j < 10; j++) {
            int q = qb + j;
            if (q < NQ) {
                float2 v = make_float2(acc[j][0], acc[j][1]);
                *reinterpret_cast<float2*>(
                    &g_P[(q * NS + s) * DD + d0 + lane * 2]) = v;
            }
        }
        __threadfence();        // release: P visible before flag bump
        __syncthreads();        // all warps' stores issued
        if (tid == 0) atomicAdd(&g_prod[c], 1);
    } else {
        // ================= Consumer: (q, d-chunk128) ========================
        const int cid = bid - NPROD;
        const int q   = cid / 5;
        const int c   = cid - q * 5;
        const int d0  = c * 128;

        for (int idx = tid; idx < NS * MM; idx += 256) {
            int sI = idx / MM, m = idx - (idx / MM) * MM;
            sm.c.W[m][sI] = w2[(sI * NQ + q) * MM + m];
        }
        for (int idx = tid; idx < 11 * MM; idx += 256) {  // zero-pad s=25..35
            int m = idx % MM, sI = NS + idx / MM;
            sm.c.W[m][sI] = 0.0f;
        }
        for (int idx = tid; idx < 128 * MM; idx += 256) {
            int d = idx / MM, m = idx - (idx / MM) * MM;
            sm.c.Q[m][d] = fm[(NS + q) * (DD * MM) + d0 * MM + idx];
        }
        __syncthreads();

        const int sb = warp * 4;   // s base (0..28), even

        float acc[4][4];
#pragma unroll
        for (int j = 0; j < 4; j++)
#pragma unroll
            for (int i = 0; i < 4; i++) acc[j][i] = 0.0f;

#pragma unroll
        for (int m = 0; m < MM; m++) {
            float4 bv = *reinterpret_cast<const float4*>(&sm.c.Q[m][lane * 4]);
            float2 av01 = *reinterpret_cast<const float2*>(&sm.c.W[m][sb]);
            float2 av23 = *reinterpret_cast<const float2*>(&sm.c.W[m][sb + 2]);
            acc[0][0] = fmaf(av01.x, bv.x, acc[0][0]);
            acc[0][1] = fmaf(av01.x, bv.y, acc[0][1]);
            acc[0][2] = fmaf(av01.x, bv.z, acc[0][2]);
            acc[0][3] = fmaf(av01.x, bv.w, acc[0][3]);
            acc[1][0] = fmaf(av01.y, bv.x, acc[1][0]);
            acc[1][1] = fmaf(av01.y, bv.y, acc[1][1]);
            acc[1][2] = fmaf(av01.y, bv.z, acc[1][2]);
            acc[1][3] = fmaf(av01.y, bv.w, acc[1][3]);
            acc[2][0] = fmaf(av23.x, bv.x, acc[2][0]);
            acc[2][1] = fmaf(av23.x, bv.y, acc[2][1]);
            acc[2][2] = fmaf(av23.x, bv.z, acc[2][2]);
            acc[2][3] = fmaf(av23.x, bv.w, acc[2][3]);
            acc[3][0] = fmaf(av23.y, bv.x, acc[3][0]);
            acc[3][1] = fmaf(av23.y, bv.y, acc[3][1]);
            acc[3][2] = fmaf(av23.y, bv.z, acc[3][2]);
            acc[3][3] = fmaf(av23.y, bv.w, acc[3][3]);
        }

        // Wait for the two producer chunk64s covering [d0, d0+128).
        if (tid == 0) {
            while (*(volatile int*)&g_prod[2 * c]     < NS) __nanosleep(64);
            while (*(volatile int*)&g_prod[2 * c + 1] < NS) __nanosleep(64);
        }
        __syncthreads();
        __threadfence();        // order P reads after flag observation

        // Epilogue: (r - p)^2 per owned s, lane reduce, plain STG partial.
#pragma unroll
        for (int j = 0; j < 4; j++) {
            int sI = sb + j;
            if (sI < NS) {
                float4 pv = __ldcg(reinterpret_cast<const float4*>(
                    &g_P[(q * NS + sI) * DD + d0 + lane * 4]));
                float t0 = acc[j][0] - pv.x;
                float t1 = acc[j][1] - pv.y;
                float t2 = acc[j][2] - pv.z;
                float t3 = acc[j][3] - pv.w;
                float part = t0 * t0 + t1 * t1 + t2 * t2 + t3 * t3;
#pragma unroll
                for (int off = 16; off > 0; off >>= 1)
                    part += __shfl_down_sync(0xffffffffu, part, off);
                if (lane == 0)
                    g_part[(q * NS + sI) * 8 + c] = part;
            }
        }

        // Last consumer of this chunk resets the flags for the next replay.
        __syncthreads();
        if (tid == 0) {
            int oc = atomicAdd(&g_cons[c], 1);
            if (oc == NQ - 1) {
                g_prod[2 * c]     = 0;
                g_prod[2 * c + 1] = 0;
                g_cons[c]         = 0;
            }
        }
    }
}

// ---------------------------------------------------------------------------
// Kernel 3: sum 5 partials per (q,s), scale, log-softmax over s.
// grid = 75, block = 32 (one warp per query row).
// ---------------------------------------------------------------------------
__global__ void k3_softmax(const float* __restrict__ scale,
                           float* __restrict__ out) {
    const int q    = blockIdx.x;
    const int lane = threadIdx.x;

    const float c = -scale[0] / 312500.0f;  // 1/(M^2 * G*Q*Q*SHOT)

    float raw = 0.0f;
    if (lane < NS) {
        const float* p = &g_part[(q * NS + lane) * 8];
        float4 v = *reinterpret_cast<const float4*>(p);   // chunks 0..3
        raw = v.x + v.y + v.z + v.w + p[4];               // + chunk 4
    }
    float logit = (lane < NS) ? raw * c : -FLT_MAX;

    float mx = logit;
#pragma unroll
    for (int off = 16; off > 0; off >>= 1)
        mx = fmaxf(mx, __shfl_xor_sync(0xffffffffu, mx, off));

    float e = (lane < NS) ? expf(logit - mx) : 0.0f;
    float sum = e;
#pragma unroll
    for (int off = 16; off > 0; off >>= 1)
        sum += __shfl_xor_sync(0xffffffffu, sum, off);

    if (lane < NS)
        out[q * NS + lane] = logit - mx - logf(sum);
}

// ---------------------------------------------------------------------------
extern "C" void kernel_launch(void* const* d_in, const int* in_sizes, int n_in,
                              void* d_out, int out_size) {
    const float* fm    = (const float*)d_in[0];  // (100, 640, 25) f32
    const float* w2    = (const float*)d_in[1];  // (25, 75, 25) f32
    const float* scale = (const float*)d_in[2];  // (1,) f32
    float* out = (float*)d_out;                  // (75, 25) f32

    fused_pc<<<NPROD + NCONS, 256>>>(fm, w2);
    k3_softmax<<<NQ, 32>>>(scale, out);
}

// round 12
// speedup vs baseline: 1.0186x; 1.0186x over previous
#include <cuda_runtime.h>
#include <math.h>
#include <float.h>

// Problem constants
#define NS 25      // support count (WAY*SHOT)
#define NQ 75      // query count (WAY*QUERY_SHOT)
#define DD 640     // feature dim
#define MM 25      // M (inner dim)

#define NPROD 250  // producer blocks: 25 s x 10 d-chunks of 64
#define NCONS 375  // consumer blocks: 75 q x 5 d-chunks of 128

// Scratch (device globals; counters return to 0 within each launch)
__device__ float g_P[NQ * NS * DD];    // P[q][s][d] = sum_m S[s,d,m]*W[s,q,m]
__device__ float g_part[NQ * NS * 8];  // per-(q,s): 5 chunk partials (pad 8)
__device__ int   g_prod[16];           // producer-done count per d-chunk64
__device__ int   g_cons[8];            // consumer-done count per d-chunk128
__device__ int   g_cnt[NQ];            // softmax tickets per q

struct SmemProd {                      // 14.8 KB
    float W[MM][80];                   // [m][q], zero-padded to 80
    float S[MM][68];                   // [m][d64] (+pad)
};
struct SmemCons {                      // 16.8 KB
    float W[MM][36];                   // [m][s], zero-padded to 36
    float Q[MM][132];                  // [m][d128] (+pad)
};

// ---------------------------------------------------------------------------
// Single fused kernel: 625 blocks x 256 threads, ALL co-resident
// (__launch_bounds__(256,5): threads 8, smem 227/16.9 = 13, regs<=51 -> >=5;
// capacity 148*5 = 740 > 625). Producers (s, d64) fill g_P; consumers
// (q, d128) run their independent r-GEMM first, spin briefly on the two
// producer flags, do the (p-r)^2 epilogue to g_part, and the LAST consumer
// block per q (ticket) computes the 25-wide log-softmax inline.
// ---------------------------------------------------------------------------
__global__ __launch_bounds__(256, 5) void fused_all(
        const float* __restrict__ fm, const float* __restrict__ w2,
        const float* __restrict__ scale, float* __restrict__ out) {
    __shared__ __align__(16) union { SmemProd p; SmemCons c; } sm;
    __shared__ int s_last;

    const int bid  = blockIdx.x;
    const int tid  = threadIdx.x;
    const int lane = tid & 31;
    const int warp = tid >> 5;   // 0..7

    if (bid < NPROD) {
        // ================= Producer: (s, d-chunk64) =========================
        const int s  = bid / 10;
        const int c  = bid - s * 10;
        const int d0 = c * 64;

        for (int idx = tid; idx < NQ * MM; idx += 256) {
            int q = idx / MM, m = idx - (idx / MM) * MM;
            sm.p.W[m][q] = w2[s * (NQ * MM) + idx];
        }
        for (int idx = tid; idx < 5 * MM; idx += 256) {   // zero-pad q=75..79
            int m = idx % MM, q = NQ + idx / MM;
            sm.p.W[m][q] = 0.0f;
        }
        for (int idx = tid; idx < 64 * MM; idx += 256) {
            int d = idx / MM, m = idx - (idx / MM) * MM;
            sm.p.S[m][d] = fm[s * (DD * MM) + d0 * MM + idx];
        }
        __syncthreads();

        const int qb = warp * 10;   // q base (0..70); warp 7 partly padded

        float acc[10][2];
#pragma unroll
        for (int j = 0; j < 10; j++) { acc[j][0] = 0.0f; acc[j][1] = 0.0f; }

#pragma unroll
        for (int m = 0; m < MM; m++) {
            float2 bv = *reinterpret_cast<const float2*>(&sm.p.S[m][lane * 2]);
#pragma unroll
            for (int jj = 0; jj < 5; jj++) {
                float2 av = *reinterpret_cast<const float2*>(
                    &sm.p.W[m][qb + 2 * jj]);               // LDS.64 broadcast
                acc[2*jj][0]   = fmaf(av.x, bv.x, acc[2*jj][0]);
                acc[2*jj][1]   = fmaf(av.x, bv.y, acc[2*jj][1]);
                acc[2*jj+1][0] = fmaf(av.y, bv.x, acc[2*jj+1][0]);
                acc[2*jj+1][1] = fmaf(av.y, bv.y, acc[2*jj+1][1]);
            }
        }

#pragma unroll
        for (int j = 0; j < 10; j++) {
            int q = qb + j;
            if (q < NQ) {
                float2 v = make_float2(acc[j][0], acc[j][1]);
                *reinterpret_cast<float2*>(
                    &g_P[(q * NS + s) * DD + d0 + lane * 2]) = v;
            }
        }
        __threadfence();        // release: P visible before flag bump
        __syncthreads();        // all warps' stores issued
        if (tid == 0) atomicAdd(&g_prod[c], 1);
    } else {
        // ================= Consumer: (q, d-chunk128) ========================
        const int cid = bid - NPROD;
        const int q   = cid / 5;
        const int c   = cid - q * 5;
        const int d0  = c * 128;

        for (int idx = tid; idx < NS * MM; idx += 256) {
            int sI = idx / MM, m = idx - (idx / MM) * MM;
            sm.c.W[m][sI] = w2[(sI * NQ + q) * MM + m];
        }
        for (int idx = tid; idx < 11 * MM; idx += 256) {  // zero-pad s=25..35
            int m = idx % MM, sI = NS + idx / MM;
            sm.c.W[m][sI] = 0.0f;
        }
        for (int idx = tid; idx < 128 * MM; idx += 256) {
            int d = idx / MM, m = idx - (idx / MM) * MM;
            sm.c.Q[m][d] = fm[(NS + q) * (DD * MM) + d0 * MM + idx];
        }
        __syncthreads();

        const int sb = warp * 4;   // s base (0..28), even

        float acc[4][4];
#pragma unroll
        for (int j = 0; j < 4; j++)
#pragma unroll
            for (int i = 0; i < 4; i++) acc[j][i] = 0.0f;

#pragma unroll
        for (int m = 0; m < MM; m++) {
            float4 bv = *reinterpret_cast<const float4*>(&sm.c.Q[m][lane * 4]);
            float2 av01 = *reinterpret_cast<const float2*>(&sm.c.W[m][sb]);
            float2 av23 = *reinterpret_cast<const float2*>(&sm.c.W[m][sb + 2]);
            acc[0][0] = fmaf(av01.x, bv.x, acc[0][0]);
            acc[0][1] = fmaf(av01.x, bv.y, acc[0][1]);
            acc[0][2] = fmaf(av01.x, bv.z, acc[0][2]);
            acc[0][3] = fmaf(av01.x, bv.w, acc[0][3]);
            acc[1][0] = fmaf(av01.y, bv.x, acc[1][0]);
            acc[1][1] = fmaf(av01.y, bv.y, acc[1][1]);
            acc[1][2] = fmaf(av01.y, bv.z, acc[1][2]);
            acc[1][3] = fmaf(av01.y, bv.w, acc[1][3]);
            acc[2][0] = fmaf(av23.x, bv.x, acc[2][0]);
            acc[2][1] = fmaf(av23.x, bv.y, acc[2][1]);
            acc[2][2] = fmaf(av23.x, bv.z, acc[2][2]);
            acc[2][3] = fmaf(av23.x, bv.w, acc[2][3]);
            acc[3][0] = fmaf(av23.y, bv.x, acc[3][0]);
            acc[3][1] = fmaf(av23.y, bv.y, acc[3][1]);
            acc[3][2] = fmaf(av23.y, bv.z, acc[3][2]);
            acc[3][3] = fmaf(av23.y, bv.w, acc[3][3]);
        }

        // Wait for the two producer chunk64s covering [d0, d0+128).
        if (tid == 0) {
            while (*(volatile int*)&g_prod[2 * c]     < NS) __nanosleep(64);
            while (*(volatile int*)&g_prod[2 * c + 1] < NS) __nanosleep(64);
        }
        __syncthreads();
        __threadfence();        // order P reads after flag observation

        // Epilogue: (r - p)^2 per owned s, lane reduce, plain STG partial.
#pragma unroll
        for (int j = 0; j < 4; j++) {
            int sI = sb + j;
            if (sI < NS) {
                float4 pv = __ldcg(reinterpret_cast<const float4*>(
                    &g_P[(q * NS + sI) * DD + d0 + lane * 4]));
                float t0 = acc[j][0] - pv.x;
                float t1 = acc[j][1] - pv.y;
                float t2 = acc[j][2] - pv.z;
                float t3 = acc[j][3] - pv.w;
                float part = t0 * t0 + t1 * t1 + t2 * t2 + t3 * t3;
#pragma unroll
                for (int off = 16; off > 0; off >>= 1)
                    part += __shfl_down_sync(0xffffffffu, part, off);
                if (lane == 0)
                    g_part[(q * NS + sI) * 8 + c] = part;
            }
        }

        // Ticket + chunk-flag reset. Release partials, then grab ticket.
        __threadfence();
        __syncthreads();
        if (tid == 0) {
            int oc = atomicAdd(&g_cons[c], 1);
            if (oc == NQ - 1) {           // last consumer of this d-chunk
                g_prod[2 * c]     = 0;    // reset for next replay
                g_prod[2 * c + 1] = 0;
                g_cons[c]         = 0;
            }
            s_last = (atomicAdd(&g_cnt[q], 1) == 4) ? 1 : 0;
        }
        __syncthreads();

        // Last consumer block for this q: inline 25-wide log-softmax.
        if (s_last && tid < 32) {
            __threadfence();              // acquire: all 5 partial STGs visible
            const float cc = -scale[0] / 312500.0f;  // 1/(M^2 * G*Q*Q*SHOT)
            float raw = 0.0f;
            if (lane < NS) {
                const float* p = &g_part[(q * NS + lane) * 8];
                float4 v = __ldcg(reinterpret_cast<const float4*>(p));
                raw = v.x + v.y + v.z + v.w + __ldcg(&p[4]);
            }
            float logit = (lane < NS) ? raw * cc : -FLT_MAX;

            float mx = logit;
#pragma unroll
            for (int off = 16; off > 0; off >>= 1)
                mx = fmaxf(mx, __shfl_xor_sync(0xffffffffu, mx, off));

            float e = (lane < NS) ? expf(logit - mx) : 0.0f;
            float sum = e;
#pragma unroll
            for (int off = 16; off > 0; off >>= 1)
                sum += __shfl_xor_sync(0xffffffffu, sum, off);

            if (lane < NS)
                out[q * NS + lane] = logit - mx - logf(sum);
            if (lane == 0) g_cnt[q] = 0;  // reset ticket for next replay
        }
    }
}

// ---------------------------------------------------------------------------
extern "C" void kernel_launch(void* const* d_in, const int* in_sizes, int n_in,
                              void* d_out, int out_size) {
    const float* fm    = (const float*)d_in[0];  // (100, 640, 25) f32
    const float* w2    = (const float*)d_in[1];  // (25, 75, 25) f32
    const float* scale = (const float*)d_in[2];  // (1,) f32
    float* out = (float*)d_out;                  // (75, 25) f32

    fused_all<<<NPROD + NCONS, 256>>>(fm, w2, scale, out);
}